// round 4
// baseline (speedup 1.0000x reference)
#include <cuda_runtime.h>
#include <cuda_bf16.h>
#include <cstdint>
#include <math.h>

// Problem: B=128, T=512, I=64, H=512, C=10. LSTM -> last hidden -> linear.
#define BB   128
#define TT   512
#define II   64
#define HH   512
#define CC   10

#define NBLOCKS  128
#define NTHREADS 512          // 16 warps, 4 per SMSP
#define NBH      4            // hidden units per block
#define ROWS     16           // 4 gates * NBH rows per block
#define KTOT     576          // H + I
#define NCHUNK   9            // 9 x 64-k chunks

// ---------------- device globals (allocation-free scratch) ----------------
__device__ __align__(256) float g_xT[TT * II * BB];   // [t][i][b]
__device__ __align__(256) float g_h[2][HH * BB];      // h transposed [n][b], dbl buffered
__device__ unsigned g_count = 0;
__device__ unsigned g_epoch = 0;

// ---------------- shared memory layout ----------------
// w_dup : ull [576][16]  (weight duplicated into both fp32 lanes)  = 73728 B
// A     : 3 buffers x [64][128] floats (triple buffered chunks)    = 98304 B
//         red[8][16][128] aliases buffers 0..1                      (65536 B)
// bias  : [16] floats
#define WD_ULL        (KTOT * ROWS)          // 9216 ull
#define A_OFF         (WD_ULL * 2)           // float index 18432
#define CHUNK_FLOATS  (64 * BB)              // 8192
#define CHUNK_BYTES   (CHUNK_FLOATS * 4)
#define BI_OFF        (A_OFF + 3 * CHUNK_FLOATS)
#define SMEM_FLOATS   (BI_OFF + 16)
#define SMEM_BYTES    (SMEM_FLOATS * 4)      // 172160 B

// ---------------- PTX helpers ----------------
__device__ __forceinline__ void ffma2(unsigned long long& a, unsigned long long x,
                                      unsigned long long y) {
    asm("fma.rn.f32x2 %0, %1, %2, %0;" : "+l"(a) : "l"(x), "l"(y));
}
__device__ __forceinline__ void cp16(uint32_t dst, const float* src) {
    asm volatile("cp.async.cg.shared.global [%0], [%1], 16;" :: "r"(dst), "l"(src));
}
// stage one 64x128 float chunk (32 KB): 4 x 16B per thread at 512 threads
__device__ __forceinline__ void stage_chunk(uint32_t dst, const float* src, int tid) {
#pragma unroll
    for (int p = 0; p < 4; ++p) {
        int o = (tid + p * NTHREADS) * 4;
        cp16(dst + (uint32_t)o * 4u, src + o);
    }
    asm volatile("cp.async.commit_group;");
}
__device__ __forceinline__ float tanh_fast(float x) {
    float y;
    asm("tanh.approx.f32 %0, %1;" : "=f"(y) : "f"(x));
    return y;
}
__device__ __forceinline__ float sigmoid_fast(float x) {
    return 0.5f * tanh_fast(0.5f * x) + 0.5f;
}
__device__ __forceinline__ float ldcg(const float* p) {
    float v;
    asm volatile("ld.global.cg.f32 %0, [%1];" : "=f"(v) : "l"(p));
    return v;
}

// grid-wide barrier: all 128 blocks co-resident (1 per SM)
__device__ __forceinline__ void grid_sync() {
    __threadfence();
    __syncthreads();
    if (threadIdx.x == 0) {
        unsigned e = *((volatile unsigned*)&g_epoch);
        unsigned prev = atomicAdd(&g_count, 1);
        if (prev == NBLOCKS - 1) {
            g_count = 0;
            __threadfence();
            *((volatile unsigned*)&g_epoch) = e + 1;
        } else {
            while (*((volatile unsigned*)&g_epoch) == e) { __nanosleep(32); }
        }
    }
    __syncthreads();
}

// ---------------- prologue: xT[t][i][b] = x[b][0][t][i] ----------------
__global__ void __launch_bounds__(256) xpose_kernel(const float* __restrict__ x) {
    __shared__ float tile[64][129];
    const int t = blockIdx.x;
    const int tid = threadIdx.x;
#pragma unroll
    for (int p = 0; p < 8; ++p) {
        int idx = tid + p * 256;           // float4 id, 0..2047
        int b = idx >> 4, q = idx & 15;
        float4 v = *(const float4*)(x + (size_t)b * (TT * II) + (size_t)t * II + q * 4);
        tile[q * 4 + 0][b] = v.x;
        tile[q * 4 + 1][b] = v.y;
        tile[q * 4 + 2][b] = v.z;
        tile[q * 4 + 3][b] = v.w;
    }
    __syncthreads();
    float* dst = g_xT + (size_t)t * (II * BB);
#pragma unroll
    for (int p = 0; p < 8; ++p) {
        int f = tid + p * 256;             // output float4 id
        int i = f >> 5;
        int b0 = (f & 31) * 4;
        float4 v = make_float4(tile[i][b0], tile[i][b0 + 1], tile[i][b0 + 2], tile[i][b0 + 3]);
        *(float4*)(dst + (size_t)f * 4) = v;
    }
}

// ---------------- persistent LSTM ----------------
__global__ void __launch_bounds__(NTHREADS, 1)
lstm_kernel(const float* __restrict__ W_ih, const float* __restrict__ W_hh,
            const float* __restrict__ b_ih, const float* __restrict__ b_hh,
            const float* __restrict__ W_cls, const float* __restrict__ b_cls,
            float* __restrict__ out)
{
    extern __shared__ float smem[];
    unsigned long long* w_dup = (unsigned long long*)smem;       // [576][16]
    float* a_sm   = smem + A_OFF;                                 // 3 chunk buffers
    float* red    = a_sm;                                         // alias buffers 0..1
    float* bias_s = smem + BI_OFF;

    const int tid  = threadIdx.x;
    const int blk  = blockIdx.x;
    const int wid  = tid >> 5;
    const int lane = tid & 31;
    const int kp   = wid & 7;          // k partition 0..7
    const int rh   = wid >> 3;         // row half 0..1
    const int bgrp = lane >> 1;        // 16 groups of 8 batch columns
    const int rgrp = lane & 1;         // 2 groups of 4 rows within the half
    const int rbase = rh * 8 + rgrp * 4;   // first of 4 rows for this thread

    // ---- build duplicated weight slice [576 k][16 rows] in smem, once ----
    for (int idx = tid; idx < KTOT * ROWS; idx += NTHREADS) {
        int k = idx >> 4, r = idx & 15;
        int gate = r >> 2, nl = r & 3;
        int grow = gate * HH + blk * NBH + nl;
        float w = (k < HH) ? W_hh[(size_t)grow * HH + k]
                           : W_ih[(size_t)grow * II + (k - HH)];
        unsigned u = __float_as_uint(w);
        w_dup[idx] = ((unsigned long long)u << 32) | (unsigned long long)u;
    }
    if (tid < ROWS) {
        int gate = tid >> 2, nl = tid & 3;
        int grow = gate * HH + blk * NBH + nl;
        bias_s[tid] = b_ih[grow] + b_hh[grow];
    }
    // zero our slice of h0 (one element per thread)
    g_h[0][blk * (NBH * BB) + tid] = 0.0f;

    // cell state: exactly one (nl, b) element per thread
    const int nl_c = tid >> 7;
    const int b_c  = tid & 127;
    float cst = 0.0f;

    grid_sync();                       // h0 + weights visible everywhere

    const uint32_t a_base = (uint32_t)__cvta_generic_to_shared(a_sm);

    for (int t = 0; t < TT; ++t) {
        const int cur = t & 1, nxt = cur ^ 1;
        const float* hsrc = g_h[cur];
        const float* xsrc = g_xT + (size_t)t * (II * BB);

        // prefetch chunk 0 into buffer 0
        stage_chunk(a_base, hsrc, tid);

        unsigned long long acc[4][4];
#pragma unroll
        for (int j = 0; j < 4; ++j) { acc[j][0]=0ull; acc[j][1]=0ull; acc[j][2]=0ull; acc[j][3]=0ull; }

        for (int c = 0; c < NCHUNK; ++c) {
            if (c < NCHUNK - 1) {
                const float* src = (c < 7) ? (hsrc + (c + 1) * CHUNK_FLOATS) : xsrc;
                stage_chunk(a_base + (uint32_t)(((c + 1) % 3) * CHUNK_BYTES), src, tid);
                asm volatile("cp.async.wait_group 1;");
            } else {
                asm volatile("cp.async.wait_group 0;");
            }
            __syncthreads();           // chunk c staged + buffer (c+1)%3 free for all

            const float* ab = a_sm + (c % 3) * CHUNK_FLOATS;
            const unsigned long long* wb = w_dup + c * 64 * ROWS;
#pragma unroll
            for (int u = 0; u < 8; ++u) {
                const int kl = u * 8 + kp;
                const float* ar = ab + kl * BB + bgrp * 8;
                ulonglong2 h01 = *(const ulonglong2*)(ar);
                ulonglong2 h23 = *(const ulonglong2*)(ar + 4);
                const unsigned long long* wr = wb + kl * ROWS + rbase;
                ulonglong2 wA = *(const ulonglong2*)(wr);
                ulonglong2 wB = *(const ulonglong2*)(wr + 2);
                unsigned long long wv[4] = {wA.x, wA.y, wB.x, wB.y};
#pragma unroll
                for (int j = 0; j < 4; ++j) {
                    ffma2(acc[j][0], h01.x, wv[j]);
                    ffma2(acc[j][1], h01.y, wv[j]);
                    ffma2(acc[j][2], h23.x, wv[j]);
                    ffma2(acc[j][3], h23.y, wv[j]);
                }
            }
        }

        // ---- write k-split partials: red[kp][r][b] (aliases buffers 0..1;
        //      last compute chunk used buffer 2, so no conflict) ----
#pragma unroll
        for (int j = 0; j < 4; ++j) {
            float* rr = red + (kp * ROWS + rbase + j) * BB + bgrp * 8;
            *(ulonglong2*)(rr)     = make_ulonglong2(acc[j][0], acc[j][1]);
            *(ulonglong2*)(rr + 4) = make_ulonglong2(acc[j][2], acc[j][3]);
        }
        __syncthreads();

        // ---- fused reduce + gates + state update: 1 element per thread ----
        {
            float s[4];
#pragma unroll
            for (int gate = 0; gate < 4; ++gate) {
                const int r = gate * 4 + nl_c;
                float a = bias_s[r];
#pragma unroll
                for (int q = 0; q < 8; ++q)
                    a += red[(q * ROWS + r) * BB + b_c];
                s[gate] = a;
            }
            float ig = sigmoid_fast(s[0]);
            float fg = sigmoid_fast(s[1]);
            float gg = tanh_fast(s[2]);
            float og = sigmoid_fast(s[3]);
            cst = fg * cst + ig * gg;
            float hv = og * tanh_fast(cst);
            g_h[nxt][(blk * NBH + nl_c) * BB + b_c] = hv;
        }

        grid_sync();
    }

    // ---------------- epilogue: out[b][cl] = h . W_cls[cl] + b_cls ----------------
    // final h is in g_h[0]; this block handles batch b = blk
    {
        const int b = blk;
        float hv = ldcg(&g_h[0][(size_t)tid * BB + b]);   // L2 read (skip stale L1)
        float* wred = a_sm;
#pragma unroll 1
        for (int cl = 0; cl < CC; ++cl) {
            float s = hv * W_cls[(size_t)cl * HH + tid];
#pragma unroll
            for (int off = 16; off; off >>= 1)
                s += __shfl_xor_sync(0xFFFFFFFFu, s, off);
            if (lane == 0) wred[cl * 16 + wid] = s;
        }
        __syncthreads();
        if (tid < CC) {
            float s = 0.0f;
#pragma unroll
            for (int w = 0; w < 16; ++w) s += wred[tid * 16 + w];
            out[b * CC + tid] = s + b_cls[tid];
        }
    }
}

// ---------------- launch ----------------
extern "C" void kernel_launch(void* const* d_in, const int* in_sizes, int n_in,
                              void* d_out, int out_size) {
    const float* x     = (const float*)d_in[0];
    const float* W_ih  = (const float*)d_in[1];
    const float* W_hh  = (const float*)d_in[2];
    const float* b_ih  = (const float*)d_in[3];
    const float* b_hh  = (const float*)d_in[4];
    const float* W_cls = (const float*)d_in[5];
    const float* b_cls = (const float*)d_in[6];
    float* out = (float*)d_out;

    cudaFuncSetAttribute(lstm_kernel, cudaFuncAttributeMaxDynamicSharedMemorySize, SMEM_BYTES);

    xpose_kernel<<<TT, 256>>>(x);
    lstm_kernel<<<NBLOCKS, NTHREADS, SMEM_BYTES>>>(W_ih, W_hh, b_ih, b_hh, W_cls, b_cls, out);
}

// round 5
// speedup vs baseline: 1.2323x; 1.2323x over previous
#include <cuda_runtime.h>
#include <cuda_bf16.h>
#include <cstdint>
#include <math.h>

// Problem: B=128, T=512, I=64, H=512, C=10. LSTM -> last hidden -> linear.
#define BB   128
#define TT   512
#define II   64
#define HH   512
#define CC   10

#define NBLOCKS  128
#define NTHREADS 512          // 16 warps, 4 per SMSP
#define NBH      4            // hidden units per block
#define ROWS     16           // 4 gates * NBH rows per block
#define KTOT     576          // H + I
#define NCHUNK   9            // 9 x 64-k chunks
#define KPW      4            // k per warp per chunk (64 / 16 warps)

// ---------------- device globals (allocation-free scratch) ----------------
__device__ __align__(256) float g_xT[TT * II * BB];   // [t][i][b]
__device__ __align__(256) float g_h[2][HH * BB];      // h transposed [n][b], dbl buffered
__device__ unsigned g_count = 0;
__device__ unsigned g_epoch = 0;

// ---------------- shared memory layout (floats) ----------------
// w_s  : [576][16] scalar weights, k-major, rows contiguous   = 36864 B
// A    : 4 buffers x [64][128] floats                          = 131072 B
//        red[16][16][128] exactly aliases the 4 buffers
// bias : [16]
#define W_FLOATS      (KTOT * ROWS)          // 9216
#define A_OFF         W_FLOATS
#define CHUNK_FLOATS  (64 * BB)              // 8192
#define CHUNK_BYTES   (CHUNK_FLOATS * 4)
#define BI_OFF        (A_OFF + 4 * CHUNK_FLOATS)
#define SMEM_FLOATS   (BI_OFF + 16)
#define SMEM_BYTES    (SMEM_FLOATS * 4)      // 168064 B

// ---------------- PTX helpers ----------------
__device__ __forceinline__ void ffma2(unsigned long long& a, unsigned long long x,
                                      unsigned long long y) {
    asm("fma.rn.f32x2 %0, %1, %2, %0;" : "+l"(a) : "l"(x), "l"(y));
}
__device__ __forceinline__ unsigned long long dupf(float w) {
    unsigned long long d; unsigned u = __float_as_uint(w);
    asm("mov.b64 %0, {%1, %1};" : "=l"(d) : "r"(u));
    return d;
}
__device__ __forceinline__ void cp16(uint32_t dst, const float* src) {
    asm volatile("cp.async.cg.shared.global [%0], [%1], 16;" :: "r"(dst), "l"(src));
}
// stage one 64x128 float chunk (32 KB): 4 x 16B per thread at 512 threads
__device__ __forceinline__ void stage_chunk(uint32_t dst, const float* src, int tid) {
#pragma unroll
    for (int p = 0; p < 4; ++p) {
        int o = (tid + p * NTHREADS) * 4;
        cp16(dst + (uint32_t)o * 4u, src + o);
    }
    asm volatile("cp.async.commit_group;");
}
__device__ __forceinline__ float tanh_fast(float x) {
    float y;
    asm("tanh.approx.f32 %0, %1;" : "=f"(y) : "f"(x));
    return y;
}
__device__ __forceinline__ float sigmoid_fast(float x) {
    return 0.5f * tanh_fast(0.5f * x) + 0.5f;
}
__device__ __forceinline__ float ldcg(const float* p) {
    float v;
    asm volatile("ld.global.cg.f32 %0, [%1];" : "=f"(v) : "l"(p));
    return v;
}

// grid-wide barrier: all 128 blocks co-resident (1 per SM)
__device__ __forceinline__ void grid_sync() {
    __threadfence();
    __syncthreads();
    if (threadIdx.x == 0) {
        unsigned e = *((volatile unsigned*)&g_epoch);
        unsigned prev = atomicAdd(&g_count, 1);
        if (prev == NBLOCKS - 1) {
            g_count = 0;
            __threadfence();
            *((volatile unsigned*)&g_epoch) = e + 1;
        } else {
            while (*((volatile unsigned*)&g_epoch) == e) { __nanosleep(32); }
        }
    }
    __syncthreads();
}

// ---------------- prologue: xT[t][i][b] = x[b][0][t][i] ----------------
__global__ void __launch_bounds__(256) xpose_kernel(const float* __restrict__ x) {
    __shared__ float tile[64][129];
    const int t = blockIdx.x;
    const int tid = threadIdx.x;
#pragma unroll
    for (int p = 0; p < 8; ++p) {
        int idx = tid + p * 256;           // float4 id, 0..2047
        int b = idx >> 4, q = idx & 15;
        float4 v = *(const float4*)(x + (size_t)b * (TT * II) + (size_t)t * II + q * 4);
        tile[q * 4 + 0][b] = v.x;
        tile[q * 4 + 1][b] = v.y;
        tile[q * 4 + 2][b] = v.z;
        tile[q * 4 + 3][b] = v.w;
    }
    __syncthreads();
    float* dst = g_xT + (size_t)t * (II * BB);
#pragma unroll
    for (int p = 0; p < 8; ++p) {
        int f = tid + p * 256;             // output float4 id
        int i = f >> 5;
        int b0 = (f & 31) * 4;
        float4 v = make_float4(tile[i][b0], tile[i][b0 + 1], tile[i][b0 + 2], tile[i][b0 + 3]);
        *(float4*)(dst + (size_t)f * 4) = v;
    }
}

// ---------------- persistent LSTM ----------------
__global__ void __launch_bounds__(NTHREADS, 1)
lstm_kernel(const float* __restrict__ W_ih, const float* __restrict__ W_hh,
            const float* __restrict__ b_ih, const float* __restrict__ b_hh,
            const float* __restrict__ W_cls, const float* __restrict__ b_cls,
            float* __restrict__ out)
{
    extern __shared__ float smem[];
    float* w_s    = smem;                              // [576][16] scalar
    float* a_sm   = smem + A_OFF;                      // 4 chunk buffers
    float* red    = a_sm;                              // [16][16][128] aliases all 4
    float* bias_s = smem + BI_OFF;

    const int tid  = threadIdx.x;
    const int blk  = blockIdx.x;
    const int wid  = tid >> 5;         // warp id = k sub-slot 0..15
    const int lane = tid & 31;
    const int b0   = lane * 4;         // 4 batch columns per thread

    // ---- load scalar weight slice [576 k][16 rows] into smem, once ----
    for (int idx = tid; idx < KTOT * ROWS; idx += NTHREADS) {
        int k = idx >> 4, r = idx & 15;
        int gate = r >> 2, nl = r & 3;
        int grow = gate * HH + blk * NBH + nl;
        w_s[idx] = (k < HH) ? W_hh[(size_t)grow * HH + k]
                            : W_ih[(size_t)grow * II + (k - HH)];
    }
    if (tid < ROWS) {
        int gate = tid >> 2, nl = tid & 3;
        int grow = gate * HH + blk * NBH + nl;
        bias_s[tid] = b_ih[grow] + b_hh[grow];
    }
    // zero our slice of h0 (one element per thread)
    g_h[0][blk * (NBH * BB) + tid] = 0.0f;

    // cell state: exactly one (nl, b) element per thread
    const int nl_c = tid >> 7;
    const int b_c  = tid & 127;
    float cst = 0.0f;

    grid_sync();                       // h0 + weights visible everywhere

    const uint32_t a_base = (uint32_t)__cvta_generic_to_shared(a_sm);
    const unsigned long long* w_ull = (const unsigned long long*)w_s;  // [k][8] row-pairs

    for (int t = 0; t < TT; ++t) {
        const int cur = t & 1, nxt = cur ^ 1;
        const float* hsrc = g_h[cur];
        const float* xsrc = g_xT + (size_t)t * (II * BB);

        // prefetch chunks 0,1 (depth-2 pipeline)
        stage_chunk(a_base, hsrc, tid);
        stage_chunk(a_base + CHUNK_BYTES, hsrc + CHUNK_FLOATS, tid);

        // acc[j][p]: rows (2j, 2j+1) packed in f32x2, batch b0+p
        unsigned long long acc[8][4];
#pragma unroll
        for (int j = 0; j < 8; ++j) { acc[j][0]=0ull; acc[j][1]=0ull; acc[j][2]=0ull; acc[j][3]=0ull; }

        for (int c = 0; c < NCHUNK; ++c) {
            if (c < NCHUNK - 2) {
                const float* src = (c + 2 < 8) ? (hsrc + (c + 2) * CHUNK_FLOATS) : xsrc;
                stage_chunk(a_base + (uint32_t)(((c + 2) & 3) * CHUNK_BYTES), src, tid);
                asm volatile("cp.async.wait_group 2;");
            } else if (c == NCHUNK - 2) {
                asm volatile("cp.async.wait_group 1;");
            } else {
                asm volatile("cp.async.wait_group 0;");
            }
            __syncthreads();           // chunk c staged; buffer (c+2)&3 free for all

            const float* ab = a_sm + (c & 3) * CHUNK_FLOATS;
            const unsigned long long* wb = w_ull + (size_t)(c * 64) * 8;
#pragma unroll
            for (int u = 0; u < KPW; ++u) {
                const int kl = wid * KPW + u;
                float4 av = *(const float4*)(ab + kl * BB + b0);
                unsigned long long ad[4] = {dupf(av.x), dupf(av.y), dupf(av.z), dupf(av.w)};
                const ulonglong2* wr = (const ulonglong2*)(wb + kl * 8);
                ulonglong2 wA = wr[0], wB = wr[1], wC = wr[2], wD = wr[3];
                unsigned long long wv[8] = {wA.x, wA.y, wB.x, wB.y, wC.x, wC.y, wD.x, wD.y};
#pragma unroll
                for (int j = 0; j < 8; ++j) {
#pragma unroll
                    for (int p = 0; p < 4; ++p)
                        ffma2(acc[j][p], ad[p], wv[j]);
                }
            }
        }

        __syncthreads();   // all compute done; buffers reusable as red

        // ---- write k-split partials: red[wid][r][b], one STS.128 per row ----
#pragma unroll
        for (int j = 0; j < 8; ++j) {
            float2 a0 = *(float2*)&acc[j][0];
            float2 a1 = *(float2*)&acc[j][1];
            float2 a2 = *(float2*)&acc[j][2];
            float2 a3 = *(float2*)&acc[j][3];
            float* r0 = red + ((wid * ROWS + 2 * j) * BB) + b0;
            float* r1 = r0 + BB;
            *(float4*)r0 = make_float4(a0.x, a1.x, a2.x, a3.x);
            *(float4*)r1 = make_float4(a0.y, a1.y, a2.y, a3.y);
        }
        __syncthreads();

        // ---- fused reduce + gates + state update: 1 element per thread ----
        {
            float s[4];
#pragma unroll
            for (int gate = 0; gate < 4; ++gate) {
                const int r = gate * 4 + nl_c;
                float a = bias_s[r];
#pragma unroll
                for (int q = 0; q < 16; ++q)
                    a += red[(q * ROWS + r) * BB + b_c];
                s[gate] = a;
            }
            float ig = sigmoid_fast(s[0]);
            float fg = sigmoid_fast(s[1]);
            float gg = tanh_fast(s[2]);
            float og = sigmoid_fast(s[3]);
            cst = fg * cst + ig * gg;
            float hv = og * tanh_fast(cst);
            g_h[nxt][(blk * NBH + nl_c) * BB + b_c] = hv;
        }

        grid_sync();
    }

    // ---------------- epilogue: out[b][cl] = h . W_cls[cl] + b_cls ----------------
    // final h is in g_h[0]; this block handles batch b = blk
    {
        const int b = blk;
        float hv = ldcg(&g_h[0][(size_t)tid * BB + b]);   // L2 read (skip stale L1)
        float* wred = a_sm;
#pragma unroll 1
        for (int cl = 0; cl < CC; ++cl) {
            float s = hv * W_cls[(size_t)cl * HH + tid];
#pragma unroll
            for (int off = 16; off; off >>= 1)
                s += __shfl_xor_sync(0xFFFFFFFFu, s, off);
            if (lane == 0) wred[cl * 16 + wid] = s;
        }
        __syncthreads();
        if (tid < CC) {
            float s = 0.0f;
#pragma unroll
            for (int w = 0; w < 16; ++w) s += wred[tid * 16 + w];
            out[b * CC + tid] = s + b_cls[tid];
        }
    }
}

// ---------------- launch ----------------
extern "C" void kernel_launch(void* const* d_in, const int* in_sizes, int n_in,
                              void* d_out, int out_size) {
    const float* x     = (const float*)d_in[0];
    const float* W_ih  = (const float*)d_in[1];
    const float* W_hh  = (const float*)d_in[2];
    const float* b_ih  = (const float*)d_in[3];
    const float* b_hh  = (const float*)d_in[4];
    const float* W_cls = (const float*)d_in[5];
    const float* b_cls = (const float*)d_in[6];
    float* out = (float*)d_out;

    cudaFuncSetAttribute(lstm_kernel, cudaFuncAttributeMaxDynamicSharedMemorySize, SMEM_BYTES);

    xpose_kernel<<<TT, 256>>>(x);
    lstm_kernel<<<NBLOCKS, NTHREADS, SMEM_BYTES>>>(W_ih, W_hh, b_ih, b_hh, W_cls, b_cls, out);
}

// round 7
// speedup vs baseline: 1.8259x; 1.4817x over previous
#include <cuda_runtime.h>
#include <cuda_bf16.h>
#include <cstdint>

// Problem: B=128, T=512, I=64, H=512, C=10.
#define BB 128
#define TT 512
#define II 64
#define HH 512
#define CC 10

#define NB 128        // persistent blocks, 1 per SM
#define NT 128        // 4 warps
#define MT 64         // gate-rows per block (16 cells x 4 gates interleaved)
#define NTb 32        // batch cols per block
#define KTOT 576
#define KW 144        // k per warp
#define KSTEPS 9      // k16 steps per warp
#define RS 584        // padded row stride (bf16) -> 1168 B, conflict-free ldmatrix
#define RSB 1168

// ---------------- smem layout (bytes) ----------------
#define SM_WHI   0
#define W_BYTES  (MT * RSB)                 // 74752
#define SM_WLO   (SM_WHI + W_BYTES)
#define SM_AHI   (SM_WLO + W_BYTES)         // 149504
#define A_BYTES  (NTb * RSB)                // 37376
#define SM_ALO   (SM_AHI + A_BYTES)
#define SM_BIAS  (SM_ALO + A_BYTES)         // 224256 ; 64 floats
#define SM_RED   (SM_BIAS + 256)            // 10*4 floats classifier scratch
#define SMEM_TOTAL (SM_RED + 256)
// pre-activation partials alias the act region: pre[w][64][36] floats = 36864 B
#define SM_PRE   SM_AHI
#define PRE_STRIDE 36

// ---------------- device globals ----------------
__device__ __align__(256) __nv_bfloat16 g_x_hi[TT * BB * II];   // [t][b][i]
__device__ __align__(256) __nv_bfloat16 g_x_lo[TT * BB * II];
__device__ __align__(256) __nv_bfloat16 g_h_hi[2][BB * HH];     // [b][n]
__device__ __align__(256) __nv_bfloat16 g_h_lo[2][BB * HH];
__device__ __align__(256) float g_h32[BB * HH];                 // [b][n] final h
__device__ unsigned g_count = 0;
__device__ unsigned g_epoch = 0;

// ---------------- helpers ----------------
__device__ __forceinline__ uint32_t smem_u32(const void* p) {
    uint32_t a;
    asm("{ .reg .u64 t; cvta.to.shared.u64 t, %1; cvt.u32.u64 %0, t; }" : "=r"(a) : "l"(p));
    return a;
}
__device__ __forceinline__ void cp16(uint32_t dst, const void* src) {
    asm volatile("cp.async.cg.shared.global [%0], [%1], 16;" :: "r"(dst), "l"(src));
}
__device__ __forceinline__ void ldm4(uint32_t* r, uint32_t addr) {
    asm volatile("ldmatrix.sync.aligned.m8n8.x4.shared.b16 {%0,%1,%2,%3}, [%4];"
                 : "=r"(r[0]), "=r"(r[1]), "=r"(r[2]), "=r"(r[3]) : "r"(addr));
}
__device__ __forceinline__ void mma16816(float* c, const uint32_t* a, const uint32_t* b) {
    asm volatile("mma.sync.aligned.m16n8k16.row.col.f32.bf16.bf16.f32 "
                 "{%0,%1,%2,%3}, {%4,%5,%6,%7}, {%8,%9}, {%0,%1,%2,%3};"
                 : "+f"(c[0]), "+f"(c[1]), "+f"(c[2]), "+f"(c[3])
                 : "r"(a[0]), "r"(a[1]), "r"(a[2]), "r"(a[3]), "r"(b[0]), "r"(b[1]));
}
__device__ __forceinline__ float tanh_fast(float x) {
    float y; asm("tanh.approx.f32 %0, %1;" : "=f"(y) : "f"(x)); return y;
}
__device__ __forceinline__ float sigmoid_fast(float x) { return 0.5f * tanh_fast(0.5f * x) + 0.5f; }
__device__ __forceinline__ float ldcg(const float* p) {
    float v; asm volatile("ld.global.cg.f32 %0, [%1];" : "=f"(v) : "l"(p)); return v;
}

// grid barrier: 128 co-resident blocks
__device__ __forceinline__ void grid_sync() {
    __threadfence();
    __syncthreads();
    if (threadIdx.x == 0) {
        unsigned e = *((volatile unsigned*)&g_epoch);
        unsigned prev = atomicAdd(&g_count, 1);
        if (prev == NB - 1) {
            g_count = 0;
            __threadfence();
            *((volatile unsigned*)&g_epoch) = e + 1;
        } else {
            while (*((volatile unsigned*)&g_epoch) == e) { __nanosleep(32); }
        }
    }
    __syncthreads();
}

// ---------------- prologue: split x into bf16 hi/lo, layout [t][b][i] ----------------
__global__ void __launch_bounds__(256) xsplit_kernel(const float* __restrict__ x) {
    int gid = blockIdx.x * 256 + threadIdx.x;       // [t][b][i]
    int i = gid & 63, b = (gid >> 6) & 127, t = gid >> 13;
    float v = x[((size_t)b * TT + t) * II + i];
    __nv_bfloat16 hi = __float2bfloat16(v);
    g_x_hi[gid] = hi;
    g_x_lo[gid] = __float2bfloat16(v - __bfloat162float(hi));
}

// ---------------- persistent LSTM (mma.sync bf16, 3-term split) ----------------
__global__ void __launch_bounds__(NT, 1)
lstm_kernel(const float* __restrict__ W_ih, const float* __restrict__ W_hh,
            const float* __restrict__ b_ih, const float* __restrict__ b_hh,
            const float* __restrict__ W_cls, const float* __restrict__ b_cls,
            float* __restrict__ out)
{
    extern __shared__ __align__(1024) char smem[];
    const uint32_t sb = smem_u32(smem);
    float* bias_s = (float*)(smem + SM_BIAS);
    float* pre    = (float*)(smem + SM_PRE);      // [4][64][36]

    const int tid  = threadIdx.x;
    const int wid  = tid >> 5;          // warp = k partition 0..3
    const int lane = tid & 31;
    const int blk  = blockIdx.x;
    const int mt   = blk >> 2;          // 32 m-groups (16 cells each)
    const int nt   = blk & 3;           // 4 batch groups (32 each)

    // ---- weight prologue: split to bf16 hi/lo in smem, rows padded to 584 ----
    // row r = 4*hidl + gate ; global gate row = gate*512 + mt*16 + hidl
    for (int idx = tid; idx < MT * KTOT; idx += NT) {
        int r = idx / KTOT, k = idx - r * KTOT;
        int gate = r & 3, hidl = r >> 2;
        int grow = gate * HH + mt * 16 + hidl;
        float v = (k < HH) ? W_hh[(size_t)grow * HH + k]
                           : W_ih[(size_t)grow * II + (k - HH)];
        __nv_bfloat16 hi = __float2bfloat16(v);
        __nv_bfloat16 lo = __float2bfloat16(v - __bfloat162float(hi));
        *(__nv_bfloat16*)(smem + SM_WHI + r * RSB + k * 2) = hi;
        *(__nv_bfloat16*)(smem + SM_WLO + r * RSB + k * 2) = lo;
    }
    if (tid < MT) {
        int gate = tid & 3, hidl = tid >> 2;
        int grow = gate * HH + mt * 16 + hidl;
        bias_s[tid] = b_ih[grow] + b_hh[grow];
    }
    // zero h0 hi/lo: 65536 bf16 each; (blk,tid) zeros 4 of each
    {
        size_t base = ((size_t)blk * NT + tid) * 4;
        *(unsigned long long*)(&g_h_hi[0][base]) = 0ull;
        *(unsigned long long*)(&g_h_lo[0][base]) = 0ull;
    }

    // cell state: 4 cells per thread; cid = tid*4+j -> hidl = cid>>5, b = cid&31
    const int hidl_c = (tid * 4) >> 5;
    const int b_c    = (tid * 4) & 31;
    float cst[4] = {0.f, 0.f, 0.f, 0.f};

    grid_sync();

    // ---- per-lane ldmatrix base addresses ----
    // A (weights): tile rows m0..15, lanes 0-15 -> rows, lanes 16-31 -> +8 cols
    uint32_t a_off = (uint32_t)((lane & 15) * RSB + (lane >> 4) * 16);
    // B (act): x4 loads two n-octets; row = p*16 + (lane&7) + 8*(lane>>4); +8 cols if lane bit3
    uint32_t b_off = (uint32_t)(((lane & 7) + ((lane >> 4) << 3)) * RSB + (((lane >> 3) & 1) * 16));

    const int k0w = wid * KW;
    const float* bias_v = bias_s;

    for (int t = 0; t < TT; ++t) {
        const int cur = t & 1, nxt = cur ^ 1;
        const __nv_bfloat16* hhi = g_h_hi[cur];
        const __nv_bfloat16* hlo = g_h_lo[cur];
        const __nv_bfloat16* xhi = g_x_hi + (size_t)t * (BB * II);
        const __nv_bfloat16* xlo = g_x_lo + (size_t)t * (BB * II);

        // ---- stage act hi/lo: [32 b][576 k] -> smem rows padded 584; 4608 x 16B ----
#pragma unroll
        for (int it = 0; it < 36; ++it) {
            int idx = tid + it * NT;
            int isLo = idx >= 2304;
            int rem = isLo ? idx - 2304 : idx;
            int rb = rem / 72;
            int gk = rem - rb * 72;
            const __nv_bfloat16* src;
            if (gk < 64) src = (isLo ? hlo : hhi) + (size_t)(nt * 32 + rb) * HH + gk * 8;
            else         src = (isLo ? xlo : xhi) + (size_t)(nt * 32 + rb) * II + (gk - 64) * 8;
            uint32_t dst = sb + (isLo ? SM_ALO : SM_AHI) + (uint32_t)(rb * RSB + gk * 16);
            cp16(dst, src);
        }
        asm volatile("cp.async.commit_group;");
        asm volatile("cp.async.wait_group 0;");
        __syncthreads();

        // ---- GEMM: warp k-slice [k0w, k0w+144), 3-term split, acc 64 fp32 ----
        float acc[4][4][4];
#pragma unroll
        for (int mi = 0; mi < 4; ++mi)
#pragma unroll
            for (int ni = 0; ni < 4; ++ni) {
                acc[mi][ni][0] = 0.f; acc[mi][ni][1] = 0.f;
                acc[mi][ni][2] = 0.f; acc[mi][ni][3] = 0.f;
            }

#pragma unroll
        for (int ks = 0; ks < KSTEPS; ++ks) {
            const uint32_t kb = (uint32_t)((k0w + ks * 16) * 2);
            uint32_t ah[4][4], al[4][4], bh[2][4], bl[2][4];
#pragma unroll
            for (int mi = 0; mi < 4; ++mi) {
                ldm4(ah[mi], sb + SM_WHI + (uint32_t)(mi * 16) * RSB + a_off + kb);
                ldm4(al[mi], sb + SM_WLO + (uint32_t)(mi * 16) * RSB + a_off + kb);
            }
#pragma unroll
            for (int p = 0; p < 2; ++p) {
                ldm4(bh[p], sb + SM_AHI + (uint32_t)(p * 16) * RSB + b_off + kb);
                ldm4(bl[p], sb + SM_ALO + (uint32_t)(p * 16) * RSB + b_off + kb);
            }
#pragma unroll
            for (int mi = 0; mi < 4; ++mi)
#pragma unroll
                for (int ni = 0; ni < 4; ++ni) {
                    const uint32_t* bhf = &bh[ni >> 1][(ni & 1) * 2];
                    const uint32_t* blf = &bl[ni >> 1][(ni & 1) * 2];
                    mma16816(acc[mi][ni], ah[mi], bhf);
                    mma16816(acc[mi][ni], al[mi], bhf);
                    mma16816(acc[mi][ni], ah[mi], blf);
                }
        }

        __syncthreads();    // act reads done -> pre may alias act

        // ---- store k-partials: pre[wid][row][col] ----
        {
            const int g = lane >> 2, t2 = (lane & 3) * 2;
            float* pw = pre + wid * (MT * PRE_STRIDE);
#pragma unroll
            for (int mi = 0; mi < 4; ++mi)
#pragma unroll
                for (int ni = 0; ni < 4; ++ni) {
                    int row = mi * 16 + g, col = ni * 8 + t2;
                    *(float2*)(pw + row * PRE_STRIDE + col) =
                        make_float2(acc[mi][ni][0], acc[mi][ni][1]);
                    *(float2*)(pw + (row + 8) * PRE_STRIDE + col) =
                        make_float2(acc[mi][ni][2], acc[mi][ni][3]);
                }
        }
        __syncthreads();

        // ---- reduce + gates + state update: 4 cells per thread ----
        {
            const int ng0 = mt * 16 + hidl_c;
            const int bg0 = nt * 32 + b_c;
#pragma unroll
            for (int j = 0; j < 4; ++j) {
                const int b = b_c + j;
                float s[4];
#pragma unroll
                for (int gate = 0; gate < 4; ++gate) {
                    const int r = hidl_c * 4 + gate;
                    float a = bias_v[r];
#pragma unroll
                    for (int w = 0; w < 4; ++w)
                        a += pre[w * (MT * PRE_STRIDE) + r * PRE_STRIDE + b];
                    s[gate] = a;
                }
                float ig = sigmoid_fast(s[0]);
                float fg = sigmoid_fast(s[1]);
                float gg = tanh_fast(s[2]);
                float og = sigmoid_fast(s[3]);
                cst[j] = fg * cst[j] + ig * gg;
                float hv = og * tanh_fast(cst[j]);
                __nv_bfloat16 hb = __float2bfloat16(hv);
                size_t off = (size_t)(bg0 + j) * HH + ng0;
                g_h_hi[nxt][off] = hb;
                g_h_lo[nxt][off] = __float2bfloat16(hv - __bfloat162float(hb));
                if (t == TT - 1) g_h32[off] = hv;
            }
        }

        grid_sync();
    }

    // ---------------- classifier: block handles batch b = blk ----------------
    {
        const int b = blk;
        float h[4];
#pragma unroll
        for (int p = 0; p < 4; ++p)
            h[p] = ldcg(&g_h32[(size_t)b * HH + tid + p * NT]);
        float* red = (float*)(smem + SM_RED);
#pragma unroll 1
        for (int cl = 0; cl < CC; ++cl) {
            const float* wc = W_cls + (size_t)cl * HH;
            float s = 0.f;
#pragma unroll
            for (int p = 0; p < 4; ++p)
                s += h[p] * wc[tid + p * NT];
#pragma unroll
            for (int off = 16; off; off >>= 1)
                s += __shfl_xor_sync(0xFFFFFFFFu, s, off);
            if (lane == 0) red[cl * 4 + wid] = s;
        }
        __syncthreads();
        if (tid < CC) {
            float s = 0.f;
#pragma unroll
            for (int w = 0; w < 4; ++w) s += red[tid * 4 + w];
            out[b * CC + tid] = s + b_cls[tid];
        }
    }
}

// ---------------- launch ----------------
extern "C" void kernel_launch(void* const* d_in, const int* in_sizes, int n_in,
                              void* d_out, int out_size) {
    const float* x     = (const float*)d_in[0];
    const float* W_ih  = (const float*)d_in[1];
    const float* W_hh  = (const float*)d_in[2];
    const float* b_ih  = (const float*)d_in[3];
    const float* b_hh  = (const float*)d_in[4];
    const float* W_cls = (const float*)d_in[5];
    const float* b_cls = (const float*)d_in[6];
    float* out = (float*)d_out;

    cudaFuncSetAttribute(lstm_kernel, cudaFuncAttributeMaxDynamicSharedMemorySize, SMEM_TOTAL);

    xsplit_kernel<<<(TT * BB * II) / 256, 256>>>(x);
    lstm_kernel<<<NB, NT, SMEM_TOTAL>>>(W_ih, W_hh, b_ih, b_hh, W_cls, b_cls, out);
}

// round 8
// speedup vs baseline: 2.1134x; 1.1575x over previous
#include <cuda_runtime.h>
#include <cuda_bf16.h>
#include <cstdint>

// Problem: B=128, T=512, I=64, H=512, C=10.
#define BB 128
#define TT 512
#define II 64
#define HH 512
#define CC 10

#define NB 128        // persistent blocks, 1 per SM
#define NT 256        // 8 warps: k-split 4 x m-split 2
#define MT 64         // gate-rows per block (16 cells x 4 gates interleaved)
#define NTb 32        // batch cols per block
#define KTOT 576
#define KW 144        // k per k-partition
#define KSTEPS 9      // k16 steps per k-partition
#define RSB 1168      // padded row stride bytes (584 bf16) — conflict-free ldmatrix

// ---------------- smem layout (bytes) ----------------
#define SM_WLO   0
#define W_BYTES  (MT * RSB)                 // 74752 (W_lo resident)
#define SM_AHI   W_BYTES                    // act hi [32 x 1168]
#define A_BYTES  (NTb * RSB)                // 37376
#define SM_ALO   (SM_AHI + A_BYTES)
#define SM_BIAS  (SM_ALO + A_BYTES)         // 149504 ; 64 floats
#define SM_RED   (SM_BIAS + 256)            // classifier scratch 10*8 floats
#define SMEM_TOTAL (SM_RED + 320)
// W_hi staged temporarily through the act region (74752 B = A hi+lo exactly)
#define SM_WTMP  SM_AHI
// pre-activation partials alias act region: pre[4][64][36] floats = 36864 B
#define SM_PRE   SM_AHI
#define PRE_STRIDE 36

// ---------------- device globals ----------------
__device__ __align__(256) __nv_bfloat16 g_x_hi[TT * BB * II];   // [t][b][i]
__device__ __align__(256) __nv_bfloat16 g_x_lo[TT * BB * II];
__device__ __align__(256) __nv_bfloat16 g_h_hi[2][BB * HH];     // [b][n]
__device__ __align__(256) __nv_bfloat16 g_h_lo[2][BB * HH];
__device__ __align__(256) float g_h32[BB * HH];
__device__ unsigned g_count = 0;
__device__ unsigned g_epoch = 0;

// ---------------- helpers ----------------
__device__ __forceinline__ uint32_t smem_u32(const void* p) {
    uint32_t a;
    asm("{ .reg .u64 t; cvta.to.shared.u64 t, %1; cvt.u32.u64 %0, t; }" : "=r"(a) : "l"(p));
    return a;
}
__device__ __forceinline__ void cp16(uint32_t dst, const void* src) {
    asm volatile("cp.async.cg.shared.global [%0], [%1], 16;" :: "r"(dst), "l"(src));
}
__device__ __forceinline__ void ldm4(uint32_t* r, uint32_t addr) {
    asm volatile("ldmatrix.sync.aligned.m8n8.x4.shared.b16 {%0,%1,%2,%3}, [%4];"
                 : "=r"(r[0]), "=r"(r[1]), "=r"(r[2]), "=r"(r[3]) : "r"(addr));
}
__device__ __forceinline__ void mma16816(float* c, const uint32_t* a, const uint32_t* b) {
    asm volatile("mma.sync.aligned.m16n8k16.row.col.f32.bf16.bf16.f32 "
                 "{%0,%1,%2,%3}, {%4,%5,%6,%7}, {%8,%9}, {%0,%1,%2,%3};"
                 : "+f"(c[0]), "+f"(c[1]), "+f"(c[2]), "+f"(c[3])
                 : "r"(a[0]), "r"(a[1]), "r"(a[2]), "r"(a[3]), "r"(b[0]), "r"(b[1]));
}
__device__ __forceinline__ float tanh_fast(float x) {
    float y; asm("tanh.approx.f32 %0, %1;" : "=f"(y) : "f"(x)); return y;
}
__device__ __forceinline__ float sigmoid_fast(float x) { return 0.5f * tanh_fast(0.5f * x) + 0.5f; }
__device__ __forceinline__ float ldcg(const float* p) {
    float v; asm volatile("ld.global.cg.f32 %0, [%1];" : "=f"(v) : "l"(p)); return v;
}

// grid barrier: 128 co-resident blocks
__device__ __forceinline__ void grid_sync() {
    __threadfence();
    __syncthreads();
    if (threadIdx.x == 0) {
        unsigned e = *((volatile unsigned*)&g_epoch);
        unsigned prev = atomicAdd(&g_count, 1);
        if (prev == NB - 1) {
            g_count = 0;
            __threadfence();
            *((volatile unsigned*)&g_epoch) = e + 1;
        } else {
            while (*((volatile unsigned*)&g_epoch) == e) { __nanosleep(32); }
        }
    }
    __syncthreads();
}

// ---------------- prologue: split x into bf16 hi/lo, layout [t][b][i] ----------------
__global__ void __launch_bounds__(256) xsplit_kernel(const float* __restrict__ x) {
    int gid = blockIdx.x * 256 + threadIdx.x;       // [t][b][i]
    int i = gid & 63, b = (gid >> 6) & 127, t = gid >> 13;
    float v = x[((size_t)b * TT + t) * II + i];
    __nv_bfloat16 hi = __float2bfloat16(v);
    g_x_hi[gid] = hi;
    g_x_lo[gid] = __float2bfloat16(v - __bfloat162float(hi));
}

// ---------------- persistent LSTM (mma.sync bf16, 3-term split, W_hi in regs) ----------------
__global__ void __launch_bounds__(NT, 1)
lstm_kernel(const float* __restrict__ W_ih, const float* __restrict__ W_hh,
            const float* __restrict__ b_ih, const float* __restrict__ b_hh,
            const float* __restrict__ W_cls, const float* __restrict__ b_cls,
            float* __restrict__ out)
{
    extern __shared__ __align__(1024) char smem[];
    const uint32_t sb = smem_u32(smem);
    float* bias_s = (float*)(smem + SM_BIAS);
    float* pre    = (float*)(smem + SM_PRE);      // [4][64][36]

    const int tid  = threadIdx.x;
    const int wid  = tid >> 5;
    const int lane = tid & 31;
    const int wk   = wid & 3;           // k partition 0..3
    const int wm   = wid >> 2;          // m half 0..1 (rows wm*32 .. wm*32+31)
    const int blk  = blockIdx.x;
    const int mt   = blk >> 2;          // 32 m-groups (16 cells each)
    const int nt   = blk & 3;           // 4 batch groups (32 each)

    // ---- weight prologue: W_lo resident in smem, W_hi staged then reg-loaded ----
    for (int idx = tid; idx < MT * KTOT; idx += NT) {
        int r = idx / KTOT, k = idx - r * KTOT;
        int gate = r & 3, hidl = r >> 2;
        int grow = gate * HH + mt * 16 + hidl;
        float v = (k < HH) ? W_hh[(size_t)grow * HH + k]
                           : W_ih[(size_t)grow * II + (k - HH)];
        __nv_bfloat16 hi = __float2bfloat16(v);
        __nv_bfloat16 lo = __float2bfloat16(v - __bfloat162float(hi));
        *(__nv_bfloat16*)(smem + SM_WTMP + r * RSB + k * 2) = hi;
        *(__nv_bfloat16*)(smem + SM_WLO  + r * RSB + k * 2) = lo;
    }
    if (tid < MT) {
        int gate = tid & 3, hidl = tid >> 2;
        int grow = gate * HH + mt * 16 + hidl;
        bias_s[tid] = b_ih[grow] + b_hh[grow];
    }
    __syncthreads();

    // ldmatrix offsets (layouts validated in R6)
    const uint32_t a_off = (uint32_t)((lane & 15) * RSB + (lane >> 4) * 16);
    const uint32_t b_off = (uint32_t)(((lane & 7) + ((lane >> 4) << 3)) * RSB
                                      + (((lane >> 3) & 1) * 16));
    const int k0w = wk * KW;

    // W_hi fragments -> registers (constant for all 512 steps): [mi][ks][4]
    uint32_t whi[2][KSTEPS][4];
#pragma unroll
    for (int mi = 0; mi < 2; ++mi)
#pragma unroll
        for (int ks = 0; ks < KSTEPS; ++ks)
            ldm4(whi[mi][ks], sb + SM_WTMP + (uint32_t)((wm * 2 + mi) * 16) * RSB
                                + a_off + (uint32_t)((k0w + ks * 16) * 2));
    __syncthreads();   // W_hi consumed; act region free

    // zero h0 hi/lo
    {
        size_t base = ((size_t)blk * NT + tid) * 2;
        *(unsigned*)(&g_h_hi[0][base]) = 0u;
        *(unsigned*)(&g_h_lo[0][base]) = 0u;
    }
    // cell state: 2 cells per thread
    const int hidl_c = tid >> 4;          // (tid*2)>>5
    const int b_c    = (tid * 2) & 31;
    float cst[2] = {0.f, 0.f};

    grid_sync();

    for (int t = 0; t < TT; ++t) {
        const int cur = t & 1, nxt = cur ^ 1;
        const __nv_bfloat16* hhi = g_h_hi[cur];
        const __nv_bfloat16* hlo = g_h_lo[cur];
        const __nv_bfloat16* xhi = g_x_hi + (size_t)t * (BB * II);
        const __nv_bfloat16* xlo = g_x_lo + (size_t)t * (BB * II);

        // ---- stage act hi (group 0) then act lo (group 1): 2304 granules each ----
#pragma unroll
        for (int it = 0; it < 9; ++it) {
            int idx = tid + it * NT;
            int rb = idx / 72, gk = idx - rb * 72;
            const __nv_bfloat16* src = (gk < 64)
                ? hhi + (size_t)(nt * 32 + rb) * HH + gk * 8
                : xhi + (size_t)(nt * 32 + rb) * II + (gk - 64) * 8;
            cp16(sb + SM_AHI + (uint32_t)(rb * RSB + gk * 16), src);
        }
        asm volatile("cp.async.commit_group;");
#pragma unroll
        for (int it = 0; it < 9; ++it) {
            int idx = tid + it * NT;
            int rb = idx / 72, gk = idx - rb * 72;
            const __nv_bfloat16* src = (gk < 64)
                ? hlo + (size_t)(nt * 32 + rb) * HH + gk * 8
                : xlo + (size_t)(nt * 32 + rb) * II + (gk - 64) * 8;
            cp16(sb + SM_ALO + (uint32_t)(rb * RSB + gk * 16), src);
        }
        asm volatile("cp.async.commit_group;");

        float acc[2][4][4];
#pragma unroll
        for (int mi = 0; mi < 2; ++mi)
#pragma unroll
            for (int ni = 0; ni < 4; ++ni) {
                acc[mi][ni][0] = 0.f; acc[mi][ni][1] = 0.f;
                acc[mi][ni][2] = 0.f; acc[mi][ni][3] = 0.f;
            }

        // ---- phase 1: (W_hi + W_lo) * a_hi  — overlaps a_lo staging ----
        asm volatile("cp.async.wait_group 1;");
        __syncthreads();
#pragma unroll
        for (int ks = 0; ks < KSTEPS; ++ks) {
            const uint32_t kb = (uint32_t)((k0w + ks * 16) * 2);
            uint32_t bh[2][4], al[2][4];
#pragma unroll
            for (int p = 0; p < 2; ++p)
                ldm4(bh[p], sb + SM_AHI + (uint32_t)(p * 16) * RSB + b_off + kb);
#pragma unroll
            for (int mi = 0; mi < 2; ++mi)
                ldm4(al[mi], sb + SM_WLO + (uint32_t)((wm * 2 + mi) * 16) * RSB + a_off + kb);
#pragma unroll
            for (int mi = 0; mi < 2; ++mi)
#pragma unroll
                for (int ni = 0; ni < 4; ++ni) {
                    const uint32_t* bf = &bh[ni >> 1][(ni & 1) * 2];
                    mma16816(acc[mi][ni], whi[mi][ks], bf);
                    mma16816(acc[mi][ni], al[mi], bf);
                }
        }

        // ---- phase 2: W_hi * a_lo ----
        asm volatile("cp.async.wait_group 0;");
        __syncthreads();
#pragma unroll
        for (int ks = 0; ks < KSTEPS; ++ks) {
            const uint32_t kb = (uint32_t)((k0w + ks * 16) * 2);
            uint32_t bl[2][4];
#pragma unroll
            for (int p = 0; p < 2; ++p)
                ldm4(bl[p], sb + SM_ALO + (uint32_t)(p * 16) * RSB + b_off + kb);
#pragma unroll
            for (int mi = 0; mi < 2; ++mi)
#pragma unroll
                for (int ni = 0; ni < 4; ++ni)
                    mma16816(acc[mi][ni], whi[mi][ks], &bl[ni >> 1][(ni & 1) * 2]);
        }

        __syncthreads();    // act reads done -> pre may alias act

        // ---- store k-partials: pre[wk][row][col] ----
        {
            const int g = lane >> 2, t2 = (lane & 3) * 2;
            float* pw = pre + wk * (MT * PRE_STRIDE);
#pragma unroll
            for (int mi = 0; mi < 2; ++mi)
#pragma unroll
                for (int ni = 0; ni < 4; ++ni) {
                    int row = (wm * 2 + mi) * 16 + g, col = ni * 8 + t2;
                    *(float2*)(pw + row * PRE_STRIDE + col) =
                        make_float2(acc[mi][ni][0], acc[mi][ni][1]);
                    *(float2*)(pw + (row + 8) * PRE_STRIDE + col) =
                        make_float2(acc[mi][ni][2], acc[mi][ni][3]);
                }
        }
        __syncthreads();

        // ---- reduce + gates + state update: 2 cells per thread ----
        {
            const int ng0 = mt * 16 + hidl_c;
            const int bg0 = nt * 32 + b_c;
#pragma unroll
            for (int j = 0; j < 2; ++j) {
                const int b = b_c + j;
                float s[4];
#pragma unroll
                for (int gate = 0; gate < 4; ++gate) {
                    const int r = hidl_c * 4 + gate;
                    float a = bias_s[r];
#pragma unroll
                    for (int w = 0; w < 4; ++w)
                        a += pre[w * (MT * PRE_STRIDE) + r * PRE_STRIDE + b];
                    s[gate] = a;
                }
                float ig = sigmoid_fast(s[0]);
                float fg = sigmoid_fast(s[1]);
                float gg = tanh_fast(s[2]);
                float og = sigmoid_fast(s[3]);
                cst[j] = fg * cst[j] + ig * gg;
                float hv = og * tanh_fast(cst[j]);
                __nv_bfloat16 hb = __float2bfloat16(hv);
                size_t off = (size_t)(bg0 + j) * HH + ng0;
                g_h_hi[nxt][off] = hb;
                g_h_lo[nxt][off] = __float2bfloat16(hv - __bfloat162float(hb));
                if (t == TT - 1) g_h32[off] = hv;
            }
        }

        grid_sync();
    }

    // ---------------- classifier: block handles batch b = blk ----------------
    {
        const int b = blk;
        float h[2];
#pragma unroll
        for (int p = 0; p < 2; ++p)
            h[p] = ldcg(&g_h32[(size_t)b * HH + tid + p * NT]);
        float* red = (float*)(smem + SM_RED);
#pragma unroll 1
        for (int cl = 0; cl < CC; ++cl) {
            const float* wc = W_cls + (size_t)cl * HH;
            float s = h[0] * wc[tid] + h[1] * wc[tid + NT];
#pragma unroll
            for (int off = 16; off; off >>= 1)
                s += __shfl_xor_sync(0xFFFFFFFFu, s, off);
            if (lane == 0) red[cl * 8 + wid] = s;
        }
        __syncthreads();
        if (tid < CC) {
            float s = 0.f;
#pragma unroll
            for (int w = 0; w < 8; ++w) s += red[tid * 8 + w];
            out[b * CC + tid] = s + b_cls[tid];
        }
    }
}

// ---------------- launch ----------------
extern "C" void kernel_launch(void* const* d_in, const int* in_sizes, int n_in,
                              void* d_out, int out_size) {
    const float* x     = (const float*)d_in[0];
    const float* W_ih  = (const float*)d_in[1];
    const float* W_hh  = (const float*)d_in[2];
    const float* b_ih  = (const float*)d_in[3];
    const float* b_hh  = (const float*)d_in[4];
    const float* W_cls = (const float*)d_in[5];
    const float* b_cls = (const float*)d_in[6];
    float* out = (float*)d_out;

    cudaFuncSetAttribute(lstm_kernel, cudaFuncAttributeMaxDynamicSharedMemorySize, SMEM_TOTAL);

    xsplit_kernel<<<(TT * BB * II) / 256, 256>>>(x);
    lstm_kernel<<<NB, NT, SMEM_TOTAL>>>(W_ih, W_hh, b_ih, b_hh, W_cls, b_cls, out);
}

// round 9
// speedup vs baseline: 2.1238x; 1.0049x over previous
#include <cuda_runtime.h>
#include <cuda_bf16.h>
#include <cstdint>

// Problem: B=128, T=512, I=64, H=512, C=10.
#define BB 128
#define TT 512
#define II 64
#define HH 512
#define CC 10

#define NB 128        // persistent blocks, 1 per SM
#define NT 256        // 8 warps: k-split 4 x m-split 2
#define MT 64         // gate-rows per block (16 cells x 4 gates interleaved)
#define NTb 32        // batch cols per block
#define KTOT 576
#define KW 144        // k per k-partition
#define KSTEPS 9      // k16 steps per k-partition
#define RSB 1168      // padded row stride bytes (584 bf16) — conflict-free ldmatrix

// ---------------- smem layout (bytes) ----------------
#define SM_WLO   0
#define W_BYTES  (MT * RSB)                 // 74752 (W_lo resident)
#define SM_AHI   W_BYTES                    // act hi [32 x 1168]
#define A_BYTES  (NTb * RSB)                // 37376
#define SM_ALO   (SM_AHI + A_BYTES)
#define SM_BIAS  (SM_ALO + A_BYTES)         // 149504 ; 64 floats
#define SM_RED   (SM_BIAS + 256)            // classifier scratch 10*8 floats
#define SMEM_TOTAL (SM_RED + 320)
// W_hi staged temporarily through the act region (74752 B = A hi+lo exactly)
#define SM_WTMP  SM_AHI
// pre-activation partials alias act region: pre[4][64][36] floats = 36864 B
#define SM_PRE   SM_AHI
#define PRE_STRIDE 36

// ---------------- device globals ----------------
__device__ __align__(256) __nv_bfloat16 g_x_hi[TT * BB * II];   // [t][b][i]
__device__ __align__(256) __nv_bfloat16 g_x_lo[TT * BB * II];
__device__ __align__(256) __nv_bfloat16 g_h_hi[2][BB * HH];     // [b][n]
__device__ __align__(256) __nv_bfloat16 g_h_lo[2][BB * HH];
__device__ __align__(256) float g_h32[BB * HH];
__device__ unsigned g_count = 0;
__device__ unsigned g_epoch = 0;

// ---------------- helpers ----------------
__device__ __forceinline__ uint32_t smem_u32(const void* p) {
    uint32_t a;
    asm("{ .reg .u64 t; cvta.to.shared.u64 t, %1; cvt.u32.u64 %0, t; }" : "=r"(a) : "l"(p));
    return a;
}
__device__ __forceinline__ void cp16(uint32_t dst, const void* src) {
    asm volatile("cp.async.cg.shared.global [%0], [%1], 16;" :: "r"(dst), "l"(src));
}
__device__ __forceinline__ void ldm4(uint32_t* r, uint32_t addr) {
    asm volatile("ldmatrix.sync.aligned.m8n8.x4.shared.b16 {%0,%1,%2,%3}, [%4];"
                 : "=r"(r[0]), "=r"(r[1]), "=r"(r[2]), "=r"(r[3]) : "r"(addr));
}
__device__ __forceinline__ void mma16816(float* c, const uint32_t* a, const uint32_t* b) {
    asm volatile("mma.sync.aligned.m16n8k16.row.col.f32.bf16.bf16.f32 "
                 "{%0,%1,%2,%3}, {%4,%5,%6,%7}, {%8,%9}, {%0,%1,%2,%3};"
                 : "+f"(c[0]), "+f"(c[1]), "+f"(c[2]), "+f"(c[3])
                 : "r"(a[0]), "r"(a[1]), "r"(a[2]), "r"(a[3]), "r"(b[0]), "r"(b[1]));
}
__device__ __forceinline__ float tanh_fast(float x) {
    float y; asm("tanh.approx.f32 %0, %1;" : "=f"(y) : "f"(x)); return y;
}
__device__ __forceinline__ float sigmoid_fast(float x) { return 0.5f * tanh_fast(0.5f * x) + 0.5f; }
__device__ __forceinline__ float ldcg(const float* p) {
    float v; asm volatile("ld.global.cg.f32 %0, [%1];" : "=f"(v) : "l"(p)); return v;
}

// grid barrier: 128 co-resident blocks
__device__ __forceinline__ void grid_sync() {
    __threadfence();
    __syncthreads();
    if (threadIdx.x == 0) {
        unsigned e = *((volatile unsigned*)&g_epoch);
        unsigned prev = atomicAdd(&g_count, 1);
        if (prev == NB - 1) {
            g_count = 0;
            __threadfence();
            *((volatile unsigned*)&g_epoch) = e + 1;
        } else {
            while (*((volatile unsigned*)&g_epoch) == e) { __nanosleep(32); }
        }
    }
    __syncthreads();
}

// ---------------- prologue: split x into bf16 hi/lo, layout [t][b][i] ----------------
__global__ void __launch_bounds__(256) xsplit_kernel(const float* __restrict__ x) {
    int gid = blockIdx.x * 256 + threadIdx.x;       // [t][b][i]
    int i = gid & 63, b = (gid >> 6) & 127, t = gid >> 13;
    float v = x[((size_t)b * TT + t) * II + i];
    __nv_bfloat16 hi = __float2bfloat16(v);
    g_x_hi[gid] = hi;
    g_x_lo[gid] = __float2bfloat16(v - __bfloat162float(hi));
}

// ---------------- persistent LSTM (mma.sync bf16, 3-term split, W_hi in regs) ----------------
__global__ void __launch_bounds__(NT, 1)
lstm_kernel(const float* __restrict__ W_ih, const float* __restrict__ W_hh,
            const float* __restrict__ b_ih, const float* __restrict__ b_hh,
            const float* __restrict__ W_cls, const float* __restrict__ b_cls,
            float* __restrict__ out)
{
    extern __shared__ __align__(1024) char smem[];
    const uint32_t sb = smem_u32(smem);
    float* bias_s = (float*)(smem + SM_BIAS);
    float* pre    = (float*)(smem + SM_PRE);      // [4][64][36]

    const int tid  = threadIdx.x;
    const int wid  = tid >> 5;
    const int lane = tid & 31;
    const int wk   = wid & 3;           // k partition 0..3
    const int wm   = wid >> 2;          // m half 0..1 (rows wm*32 .. wm*32+31)
    const int blk  = blockIdx.x;
    const int mt   = blk >> 2;          // 32 m-groups (16 cells each)
    const int nt   = blk & 3;           // 4 batch groups (32 each)

    // ---- weight prologue: W_lo resident in smem, W_hi staged then reg-loaded ----
    for (int idx = tid; idx < MT * KTOT; idx += NT) {
        int r = idx / KTOT, k = idx - r * KTOT;
        int gate = r & 3, hidl = r >> 2;
        int grow = gate * HH + mt * 16 + hidl;
        float v = (k < HH) ? W_hh[(size_t)grow * HH + k]
                           : W_ih[(size_t)grow * II + (k - HH)];
        __nv_bfloat16 hi = __float2bfloat16(v);
        __nv_bfloat16 lo = __float2bfloat16(v - __bfloat162float(hi));
        *(__nv_bfloat16*)(smem + SM_WTMP + r * RSB + k * 2) = hi;
        *(__nv_bfloat16*)(smem + SM_WLO  + r * RSB + k * 2) = lo;
    }
    if (tid < MT) {
        int gate = tid & 3, hidl = tid >> 2;
        int grow = gate * HH + mt * 16 + hidl;
        bias_s[tid] = b_ih[grow] + b_hh[grow];
    }
    __syncthreads();

    // ldmatrix offsets (layouts validated in R6)
    const uint32_t a_off = (uint32_t)((lane & 15) * RSB + (lane >> 4) * 16);
    const uint32_t b_off = (uint32_t)(((lane & 7) + ((lane >> 4) << 3)) * RSB
                                      + (((lane >> 3) & 1) * 16));
    const int k0w = wk * KW;

    // W_hi fragments -> registers (constant for all 512 steps): [mi][ks][4]
    uint32_t whi[2][KSTEPS][4];
#pragma unroll
    for (int mi = 0; mi < 2; ++mi)
#pragma unroll
        for (int ks = 0; ks < KSTEPS; ++ks)
            ldm4(whi[mi][ks], sb + SM_WTMP + (uint32_t)((wm * 2 + mi) * 16) * RSB
                                + a_off + (uint32_t)((k0w + ks * 16) * 2));
    __syncthreads();   // W_hi consumed; act region free

    // zero h0 hi/lo
    {
        size_t base = ((size_t)blk * NT + tid) * 2;
        *(unsigned*)(&g_h_hi[0][base]) = 0u;
        *(unsigned*)(&g_h_lo[0][base]) = 0u;
    }
    // cell state: 2 cells per thread
    const int hidl_c = tid >> 4;          // (tid*2)>>5
    const int b_c    = (tid * 2) & 31;
    float cst[2] = {0.f, 0.f};

    grid_sync();

    for (int t = 0; t < TT; ++t) {
        const int cur = t & 1, nxt = cur ^ 1;
        const __nv_bfloat16* hhi = g_h_hi[cur];
        const __nv_bfloat16* hlo = g_h_lo[cur];
        const __nv_bfloat16* xhi = g_x_hi + (size_t)t * (BB * II);
        const __nv_bfloat16* xlo = g_x_lo + (size_t)t * (BB * II);

        // ---- stage act hi (group 0) then act lo (group 1): 2304 granules each ----
#pragma unroll
        for (int it = 0; it < 9; ++it) {
            int idx = tid + it * NT;
            int rb = idx / 72, gk = idx - rb * 72;
            const __nv_bfloat16* src = (gk < 64)
                ? hhi + (size_t)(nt * 32 + rb) * HH + gk * 8
                : xhi + (size_t)(nt * 32 + rb) * II + (gk - 64) * 8;
            cp16(sb + SM_AHI + (uint32_t)(rb * RSB + gk * 16), src);
        }
        asm volatile("cp.async.commit_group;");
#pragma unroll
        for (int it = 0; it < 9; ++it) {
            int idx = tid + it * NT;
            int rb = idx / 72, gk = idx - rb * 72;
            const __nv_bfloat16* src = (gk < 64)
                ? hlo + (size_t)(nt * 32 + rb) * HH + gk * 8
                : xlo + (size_t)(nt * 32 + rb) * II + (gk - 64) * 8;
            cp16(sb + SM_ALO + (uint32_t)(rb * RSB + gk * 16), src);
        }
        asm volatile("cp.async.commit_group;");

        float acc[2][4][4];
#pragma unroll
        for (int mi = 0; mi < 2; ++mi)
#pragma unroll
            for (int ni = 0; ni < 4; ++ni) {
                acc[mi][ni][0] = 0.f; acc[mi][ni][1] = 0.f;
                acc[mi][ni][2] = 0.f; acc[mi][ni][3] = 0.f;
            }

        // ---- phase 1: (W_hi + W_lo) * a_hi  — overlaps a_lo staging ----
        asm volatile("cp.async.wait_group 1;");
        __syncthreads();
#pragma unroll
        for (int ks = 0; ks < KSTEPS; ++ks) {
            const uint32_t kb = (uint32_t)((k0w + ks * 16) * 2);
            uint32_t bh[2][4], al[2][4];
#pragma unroll
            for (int p = 0; p < 2; ++p)
                ldm4(bh[p], sb + SM_AHI + (uint32_t)(p * 16) * RSB + b_off + kb);
#pragma unroll
            for (int mi = 0; mi < 2; ++mi)
                ldm4(al[mi], sb + SM_WLO + (uint32_t)((wm * 2 + mi) * 16) * RSB + a_off + kb);
#pragma unroll
            for (int mi = 0; mi < 2; ++mi)
#pragma unroll
                for (int ni = 0; ni < 4; ++ni) {
                    const uint32_t* bf = &bh[ni >> 1][(ni & 1) * 2];
                    mma16816(acc[mi][ni], whi[mi][ks], bf);
                    mma16816(acc[mi][ni], al[mi], bf);
                }
        }

        // ---- phase 2: W_hi * a_lo ----
        asm volatile("cp.async.wait_group 0;");
        __syncthreads();
#pragma unroll
        for (int ks = 0; ks < KSTEPS; ++ks) {
            const uint32_t kb = (uint32_t)((k0w + ks * 16) * 2);
            uint32_t bl[2][4];
#pragma unroll
            for (int p = 0; p < 2; ++p)
                ldm4(bl[p], sb + SM_ALO + (uint32_t)(p * 16) * RSB + b_off + kb);
#pragma unroll
            for (int mi = 0; mi < 2; ++mi)
#pragma unroll
                for (int ni = 0; ni < 4; ++ni)
                    mma16816(acc[mi][ni], whi[mi][ks], &bl[ni >> 1][(ni & 1) * 2]);
        }

        __syncthreads();    // act reads done -> pre may alias act

        // ---- store k-partials: pre[wk][row][col] ----
        {
            const int g = lane >> 2, t2 = (lane & 3) * 2;
            float* pw = pre + wk * (MT * PRE_STRIDE);
#pragma unroll
            for (int mi = 0; mi < 2; ++mi)
#pragma unroll
                for (int ni = 0; ni < 4; ++ni) {
                    int row = (wm * 2 + mi) * 16 + g, col = ni * 8 + t2;
                    *(float2*)(pw + row * PRE_STRIDE + col) =
                        make_float2(acc[mi][ni][0], acc[mi][ni][1]);
                    *(float2*)(pw + (row + 8) * PRE_STRIDE + col) =
                        make_float2(acc[mi][ni][2], acc[mi][ni][3]);
                }
        }
        __syncthreads();

        // ---- reduce + gates + state update: 2 cells per thread ----
        {
            const int ng0 = mt * 16 + hidl_c;
            const int bg0 = nt * 32 + b_c;
#pragma unroll
            for (int j = 0; j < 2; ++j) {
                const int b = b_c + j;
                float s[4];
#pragma unroll
                for (int gate = 0; gate < 4; ++gate) {
                    const int r = hidl_c * 4 + gate;
                    float a = bias_s[r];
#pragma unroll
                    for (int w = 0; w < 4; ++w)
                        a += pre[w * (MT * PRE_STRIDE) + r * PRE_STRIDE + b];
                    s[gate] = a;
                }
                float ig = sigmoid_fast(s[0]);
                float fg = sigmoid_fast(s[1]);
                float gg = tanh_fast(s[2]);
                float og = sigmoid_fast(s[3]);
                cst[j] = fg * cst[j] + ig * gg;
                float hv = og * tanh_fast(cst[j]);
                __nv_bfloat16 hb = __float2bfloat16(hv);
                size_t off = (size_t)(bg0 + j) * HH + ng0;
                g_h_hi[nxt][off] = hb;
                g_h_lo[nxt][off] = __float2bfloat16(hv - __bfloat162float(hb));
                if (t == TT - 1) g_h32[off] = hv;
            }
        }

        grid_sync();
    }

    // ---------------- classifier: block handles batch b = blk ----------------
    {
        const int b = blk;
        float h[2];
#pragma unroll
        for (int p = 0; p < 2; ++p)
            h[p] = ldcg(&g_h32[(size_t)b * HH + tid + p * NT]);
        float* red = (float*)(smem + SM_RED);
#pragma unroll 1
        for (int cl = 0; cl < CC; ++cl) {
            const float* wc = W_cls + (size_t)cl * HH;
            float s = h[0] * wc[tid] + h[1] * wc[tid + NT];
#pragma unroll
            for (int off = 16; off; off >>= 1)
                s += __shfl_xor_sync(0xFFFFFFFFu, s, off);
            if (lane == 0) red[cl * 8 + wid] = s;
        }
        __syncthreads();
        if (tid < CC) {
            float s = 0.f;
#pragma unroll
            for (int w = 0; w < 8; ++w) s += red[tid * 8 + w];
            out[b * CC + tid] = s + b_cls[tid];
        }
    }
}

// ---------------- launch ----------------
extern "C" void kernel_launch(void* const* d_in, const int* in_sizes, int n_in,
                              void* d_out, int out_size) {
    const float* x     = (const float*)d_in[0];
    const float* W_ih  = (const float*)d_in[1];
    const float* W_hh  = (const float*)d_in[2];
    const float* b_ih  = (const float*)d_in[3];
    const float* b_hh  = (const float*)d_in[4];
    const float* W_cls = (const float*)d_in[5];
    const float* b_cls = (const float*)d_in[6];
    float* out = (float*)d_out;

    cudaFuncSetAttribute(lstm_kernel, cudaFuncAttributeMaxDynamicSharedMemorySize, SMEM_TOTAL);

    xsplit_kernel<<<(TT * BB * II) / 256, 256>>>(x);
    lstm_kernel<<<NB, NT, SMEM_TOTAL>>>(W_ih, W_hh, b_ih, b_hh, W_cls, b_cls, out);
}